// round 4
// baseline (speedup 1.0000x reference)
#include <cuda_runtime.h>
#include <cstdint>

#define BQ   2
#define NCAM 6
#define CCH  256
#define MQ   900
#define NLVL 4
#define EPSV 1e-5f
#define QPB  2            // queries per block
#define NBLK (BQ * MQ / QPB)   // 900 blocks

__constant__ int c_H[NLVL]  = {116, 58, 29, 15};
__constant__ int c_W[NLVL]  = {200, 100, 50, 25};
__constant__ int c_HW[NLVL] = {23200, 5800, 1450, 375};

#define NENT (NCAM * NLVL)

__global__ __launch_bounds__(CCH, 5)
void FeatureSampler_kernel(const float* __restrict__ f0,
                           const float* __restrict__ f1,
                           const float* __restrict__ f2,
                           const float* __restrict__ f3,
                           const float* __restrict__ refpts,
                           const float* __restrict__ l2i,
                           float* __restrict__ out)
{
    const int c = threadIdx.x;
    const int bmq[QPB] = { (int)blockIdx.x, (int)blockIdx.x + NBLK };

    __shared__ const float* s_base[QPB][NENT];
    __shared__ int   s_HW[QPB][NENT];
    __shared__ int   s_idx[QPB][NENT][4];
    __shared__ float s_w[QPB][NENT][4];
    __shared__ int   s_act[QPB][NENT];
    __shared__ float s_valid[QPB][NCAM];
    __shared__ int   s_list[QPB][NENT];
    __shared__ int   s_ne[QPB];
    __shared__ float s_cnt[QPB];

    // ---- Phase 1: threads 0..47 build entries for both queries ----
    if (threadIdx.x < QPB * NENT) {
        const int q   = threadIdx.x >= NENT;           // which query
        const int t   = threadIdx.x - q * NENT;        // entry index 0..23
        const int n   = t >> 2;                        // camera
        const int lvl = t & 3;                         // level
        const int bm  = bmq[q];
        const int b   = bm / MQ;

        const float* rp = refpts + (size_t)bm * 3;
        float rx = rp[0] * 122.4f - 61.2f;
        float ry = rp[1] * 122.4f - 61.2f;
        float rz = rp[2] * 20.0f  - 10.0f;

        const float* Mt = l2i + (size_t)(b * NCAM + n) * 16;
        float cx = Mt[0]*rx + Mt[1]*ry + Mt[2] *rz + Mt[3];
        float cy = Mt[4]*rx + Mt[5]*ry + Mt[6] *rz + Mt[7];
        float cz = Mt[8]*rx + Mt[9]*ry + Mt[10]*rz + Mt[11];

        bool vcam = (cz > EPSV);
        if (lvl == 0) s_valid[q][n] = vcam ? 1.0f : 0.0f;

        float inv = 1.0f / (cz + EPSV);
        float x = cx * inv - 0.5f;    // grid_sample denorm cancels across levels
        float y = cy * inv - 0.5f;

        const int W  = c_W[lvl];
        const int H  = c_H[lvl];
        const int HW = c_HW[lvl];

        int active = 0;
        if (vcam && (x > -1.0f) && (x < (float)W) && (y > -1.0f) && (y < (float)H)) {
            float x0f = floorf(x), y0f = floorf(y);
            float wx1 = x - x0f, wx0 = 1.0f - wx1;
            float wy1 = y - y0f, wy0 = 1.0f - wy1;

            bool vx0 = (x0f >= 0.0f)        && (x0f <= (float)(W - 1));
            bool vx1 = (x0f + 1.0f >= 0.0f) && (x0f + 1.0f <= (float)(W - 1));
            bool vy0 = (y0f >= 0.0f)        && (y0f <= (float)(H - 1));
            bool vy1 = (y0f + 1.0f >= 0.0f) && (y0f + 1.0f <= (float)(H - 1));

            int xi0 = (int)fminf(fmaxf(x0f,        0.0f), (float)(W - 1));
            int xi1 = (int)fminf(fmaxf(x0f + 1.0f, 0.0f), (float)(W - 1));
            int yi0 = (int)fminf(fmaxf(y0f,        0.0f), (float)(H - 1));
            int yi1 = (int)fminf(fmaxf(y0f + 1.0f, 0.0f), (float)(H - 1));

            float w00 = (vx0 && vy0) ? (wx0 * wy0) : 0.0f;
            float w01 = (vx1 && vy0) ? (wx1 * wy0) : 0.0f;
            float w10 = (vx0 && vy1) ? (wx0 * wy1) : 0.0f;
            float w11 = (vx1 && vy1) ? (wx1 * wy1) : 0.0f;

            if ((w00 != 0.0f) || (w01 != 0.0f) || (w10 != 0.0f) || (w11 != 0.0f)) {
                active = 1;
                const float* fl = (lvl == 0) ? f0 : (lvl == 1) ? f1 : (lvl == 2) ? f2 : f3;
                s_base[q][t]   = fl + (size_t)(b * NCAM + n) * CCH * HW;
                s_HW[q][t]     = HW;
                s_idx[q][t][0] = yi0 * W + xi0;
                s_idx[q][t][1] = yi0 * W + xi1;
                s_idx[q][t][2] = yi1 * W + xi0;
                s_idx[q][t][3] = yi1 * W + xi1;
                s_w[q][t][0] = w00;  s_w[q][t][1] = w01;
                s_w[q][t][2] = w10;  s_w[q][t][3] = w11;
            }
        }
        s_act[q][t] = active;
    }
    __syncthreads();

    // ---- Deterministic compaction: one thread per query ----
    if (threadIdx.x < QPB) {
        const int q = threadIdx.x;
        int ne = 0;
        #pragma unroll
        for (int e = 0; e < NENT; e++)
            if (s_act[q][e]) s_list[q][ne++] = e;
        s_ne[q] = ne;
        float cnt = 0.0f;
        #pragma unroll
        for (int n = 0; n < NCAM; n++) cnt += s_valid[q][n];
        s_cnt[q] = cnt;
    }
    __syncthreads();

    const int ne0 = s_ne[0];
    const int ne1 = s_ne[1];
    const int nk  = (ne0 > ne1) ? ne0 : ne1;

    // ---- Phase 2: interleaved gather over both queries (8 independent loads/iter) ----
    float acc0 = 0.0f, acc1 = 0.0f;
    for (int k = 0; k < nk; k++) {
        // query 0 slot
        const float* pA; float wA0, wA1, wA2, wA3; int iA0, iA1, iA2, iA3;
        if (k < ne0) {
            const int e = s_list[0][k];
            pA = s_base[0][e] + (size_t)c * s_HW[0][e];
            iA0 = s_idx[0][e][0]; iA1 = s_idx[0][e][1];
            iA2 = s_idx[0][e][2]; iA3 = s_idx[0][e][3];
            wA0 = s_w[0][e][0]; wA1 = s_w[0][e][1];
            wA2 = s_w[0][e][2]; wA3 = s_w[0][e][3];
        } else {
            pA = f3; iA0 = iA1 = iA2 = iA3 = 0;
            wA0 = wA1 = wA2 = wA3 = 0.0f;
        }
        // query 1 slot
        const float* pB; float wB0, wB1, wB2, wB3; int iB0, iB1, iB2, iB3;
        if (k < ne1) {
            const int e = s_list[1][k];
            pB = s_base[1][e] + (size_t)c * s_HW[1][e];
            iB0 = s_idx[1][e][0]; iB1 = s_idx[1][e][1];
            iB2 = s_idx[1][e][2]; iB3 = s_idx[1][e][3];
            wB0 = s_w[1][e][0]; wB1 = s_w[1][e][1];
            wB2 = s_w[1][e][2]; wB3 = s_w[1][e][3];
        } else {
            pB = f3; iB0 = iB1 = iB2 = iB3 = 0;
            wB0 = wB1 = wB2 = wB3 = 0.0f;
        }

        // 8 independent gathers
        float a0 = __ldg(pA + iA0);
        float a1 = __ldg(pA + iA1);
        float a2 = __ldg(pA + iA2);
        float a3 = __ldg(pA + iA3);
        float b0 = __ldg(pB + iB0);
        float b1 = __ldg(pB + iB1);
        float b2 = __ldg(pB + iB2);
        float b3 = __ldg(pB + iB3);

        acc0 += wA0*a0 + wA1*a1 + wA2*a2 + wA3*a3;
        acc1 += wB0*b0 + wB1*b1 + wB2*b2 + wB3*b3;
    }

    out[(size_t)bmq[0] * CCH + c] = acc0 * 0.25f / (s_cnt[0] + EPSV);
    out[(size_t)bmq[1] * CCH + c] = acc1 * 0.25f / (s_cnt[1] + EPSV);
}

extern "C" void kernel_launch(void* const* d_in, const int* in_sizes, int n_in,
                              void* d_out, int out_size)
{
    const float* f0  = (const float*)d_in[0];
    const float* f1  = (const float*)d_in[1];
    const float* f2  = (const float*)d_in[2];
    const float* f3  = (const float*)d_in[3];
    const float* rp  = (const float*)d_in[4];
    const float* l2i = (const float*)d_in[5];
    float* out = (float*)d_out;

    dim3 grid(NBLK);
    dim3 block(CCH);
    FeatureSampler_kernel<<<grid, block>>>(f0, f1, f2, f3, rp, l2i, out);
}

// round 5
// speedup vs baseline: 1.5124x; 1.5124x over previous
#include <cuda_runtime.h>
#include <cstdint>

#define BQ   2
#define NCAM 6
#define CCH  256
#define MQ   900
#define NLVL 4
#define EPSV 1e-5f

__constant__ int c_H[NLVL]  = {116, 58, 29, 15};
__constant__ int c_W[NLVL]  = {200, 100, 50, 25};
__constant__ int c_HW[NLVL] = {23200, 5800, 1450, 375};

#define NENT (NCAM * NLVL)

__global__ __launch_bounds__(CCH, 6)
void FeatureSampler_kernel(const float* __restrict__ f0,
                           const float* __restrict__ f1,
                           const float* __restrict__ f2,
                           const float* __restrict__ f3,
                           const float* __restrict__ refpts,
                           const float* __restrict__ l2i,
                           float* __restrict__ out)
{
    const int bm  = blockIdx.x;          // b * MQ + m
    const int b   = bm / MQ;
    const int L   = threadIdx.x & 31;    // lane
    const int wrp = threadIdx.x >> 5;    // warp 0..7

    // corner lives in low 2 lane bits -> lanes 0/1 load adjacent floats (x0,x1)
    // and coalesce into one sector; lanes 2/3 likewise for row y1.
    const int corner = L & 3;
    const int chsub  = wrp * 8 + (L >> 2);   // channel sub-index 0..63

    __shared__ const float* s_base[NENT];
    __shared__ int   s_HW[NENT];
    __shared__ int   s_idx[NENT][4];
    __shared__ float s_w[NENT][4];
    __shared__ int   s_act[NENT];
    __shared__ float s_valid[NCAM];
    __shared__ int   s_list[NENT];
    __shared__ int   s_ne;

    // ---- Phase 1: threads 0..23 build per-(camera,level) sampling entries ----
    if (threadIdx.x < NENT) {
        const int t   = threadIdx.x;
        const int n   = t >> 2;
        const int lvl = t & 3;

        const float* rp = refpts + (size_t)bm * 3;
        float rx = rp[0] * 122.4f - 61.2f;
        float ry = rp[1] * 122.4f - 61.2f;
        float rz = rp[2] * 20.0f  - 10.0f;

        const float* Mt = l2i + (size_t)(b * NCAM + n) * 16;
        float cx = Mt[0]*rx + Mt[1]*ry + Mt[2] *rz + Mt[3];
        float cy = Mt[4]*rx + Mt[5]*ry + Mt[6] *rz + Mt[7];
        float cz = Mt[8]*rx + Mt[9]*ry + Mt[10]*rz + Mt[11];

        bool vcam = (cz > EPSV);
        if (lvl == 0) s_valid[n] = vcam ? 1.0f : 0.0f;

        float inv = 1.0f / (cz + EPSV);
        float x = cx * inv - 0.5f;   // grid_sample denorm cancels across levels
        float y = cy * inv - 0.5f;

        const int W  = c_W[lvl];
        const int H  = c_H[lvl];
        const int HW = c_HW[lvl];

        int active = 0;
        if (vcam && (x > -1.0f) && (x < (float)W) && (y > -1.0f) && (y < (float)H)) {
            float x0f = floorf(x), y0f = floorf(y);
            float wx1 = x - x0f, wx0 = 1.0f - wx1;
            float wy1 = y - y0f, wy0 = 1.0f - wy1;

            bool vx0 = (x0f >= 0.0f)        && (x0f <= (float)(W - 1));
            bool vx1 = (x0f + 1.0f >= 0.0f) && (x0f + 1.0f <= (float)(W - 1));
            bool vy0 = (y0f >= 0.0f)        && (y0f <= (float)(H - 1));
            bool vy1 = (y0f + 1.0f >= 0.0f) && (y0f + 1.0f <= (float)(H - 1));

            int xi0 = (int)fminf(fmaxf(x0f,        0.0f), (float)(W - 1));
            int xi1 = (int)fminf(fmaxf(x0f + 1.0f, 0.0f), (float)(W - 1));
            int yi0 = (int)fminf(fmaxf(y0f,        0.0f), (float)(H - 1));
            int yi1 = (int)fminf(fmaxf(y0f + 1.0f, 0.0f), (float)(H - 1));

            float w00 = (vx0 && vy0) ? (wx0 * wy0) : 0.0f;
            float w01 = (vx1 && vy0) ? (wx1 * wy0) : 0.0f;
            float w10 = (vx0 && vy1) ? (wx0 * wy1) : 0.0f;
            float w11 = (vx1 && vy1) ? (wx1 * wy1) : 0.0f;

            if ((w00 != 0.0f) || (w01 != 0.0f) || (w10 != 0.0f) || (w11 != 0.0f)) {
                active = 1;
                const float* fl = (lvl == 0) ? f0 : (lvl == 1) ? f1 : (lvl == 2) ? f2 : f3;
                s_base[t]   = fl + (size_t)(b * NCAM + n) * CCH * HW;
                s_HW[t]     = HW;
                s_idx[t][0] = yi0 * W + xi0;   // corner order: (y0,x0),(y0,x1),(y1,x0),(y1,x1)
                s_idx[t][1] = yi0 * W + xi1;
                s_idx[t][2] = yi1 * W + xi0;
                s_idx[t][3] = yi1 * W + xi1;
                s_w[t][0] = w00;  s_w[t][1] = w01;
                s_w[t][2] = w10;  s_w[t][3] = w11;
            }
        }
        s_act[t] = active;
    }
    __syncthreads();

    if (threadIdx.x == 0) {
        int ne = 0;
        #pragma unroll
        for (int e = 0; e < NENT; e++)
            if (s_act[e]) s_list[ne++] = e;
        s_ne = ne;
    }
    __syncthreads();

    const float cnt = s_valid[0] + s_valid[1] + s_valid[2] +
                      s_valid[3] + s_valid[4] + s_valid[5];
    const int ne = s_ne;

    // ---- Phase 2: quad-corner gather. Each lane loads ONE corner for its
    //      channel; quads (lanes sharing L>>2) coalesce the x0/x1 pair into a
    //      single sector request. Butterfly-sum inside the quad.            ----
    float acc0 = 0.0f, acc1 = 0.0f, acc2 = 0.0f, acc3 = 0.0f;

    for (int k = 0; k < ne; k++) {
        const int e = s_list[k];
        const float* bp = s_base[e];
        const int   HW  = s_HW[e];
        const int   idx = s_idx[e][corner];
        const float wc  = s_w[e][corner];

        // 4 independent gathers (channels chsub, chsub+64, +128, +192)
        const float* p0 = bp + (size_t)chsub * HW + idx;
        float v0 = __ldg(p0);
        float v1 = __ldg(p0 + (size_t)64  * HW);
        float v2 = __ldg(p0 + (size_t)128 * HW);
        float v3 = __ldg(p0 + (size_t)192 * HW);

        float t0 = v0 * wc;
        float t1 = v1 * wc;
        float t2 = v2 * wc;
        float t3 = v3 * wc;
        // quad butterfly: sum the 4 weighted corners; every lane gets the result
        t0 += __shfl_xor_sync(0xFFFFFFFFu, t0, 1);
        t1 += __shfl_xor_sync(0xFFFFFFFFu, t1, 1);
        t2 += __shfl_xor_sync(0xFFFFFFFFu, t2, 1);
        t3 += __shfl_xor_sync(0xFFFFFFFFu, t3, 1);
        t0 += __shfl_xor_sync(0xFFFFFFFFu, t0, 2);
        t1 += __shfl_xor_sync(0xFFFFFFFFu, t1, 2);
        t2 += __shfl_xor_sync(0xFFFFFFFFu, t2, 2);
        t3 += __shfl_xor_sync(0xFFFFFFFFu, t3, 2);
        acc0 += t0;  acc1 += t1;  acc2 += t2;  acc3 += t3;
    }

    if (corner == 0) {
        const float s = 0.25f / (cnt + EPSV);
        float* o = out + (size_t)bm * CCH + chsub;
        o[0]   = acc0 * s;
        o[64]  = acc1 * s;
        o[128] = acc2 * s;
        o[192] = acc3 * s;
    }
}

extern "C" void kernel_launch(void* const* d_in, const int* in_sizes, int n_in,
                              void* d_out, int out_size)
{
    const float* f0  = (const float*)d_in[0];
    const float* f1  = (const float*)d_in[1];
    const float* f2  = (const float*)d_in[2];
    const float* f3  = (const float*)d_in[3];
    const float* rp  = (const float*)d_in[4];
    const float* l2i = (const float*)d_in[5];
    float* out = (float*)d_out;

    dim3 grid(BQ * MQ);
    dim3 block(CCH);
    FeatureSampler_kernel<<<grid, block>>>(f0, f1, f2, f3, rp, l2i, out);
}

// round 6
// speedup vs baseline: 1.6339x; 1.0804x over previous
#include <cuda_runtime.h>
#include <cstdint>

#define BQ   2
#define NCAM 6
#define CCH  256
#define MQ   900
#define NLVL 4
#define EPSV 1e-5f

__constant__ int c_H[NLVL]  = {116, 58, 29, 15};
__constant__ int c_W[NLVL]  = {200, 100, 50, 25};
__constant__ int c_HW[NLVL] = {23200, 5800, 1450, 375};

#define NENT (NCAM * NLVL)

__global__ __launch_bounds__(CCH, 6)
void FeatureSampler_kernel(const float* __restrict__ f0,
                           const float* __restrict__ f1,
                           const float* __restrict__ f2,
                           const float* __restrict__ f3,
                           const float* __restrict__ refpts,
                           const float* __restrict__ l2i,
                           float* __restrict__ out)
{
    const int bm  = blockIdx.x;          // b * MQ + m
    const int b   = bm / MQ;
    const int L   = threadIdx.x & 31;    // lane
    const int wrp = threadIdx.x >> 5;    // warp 0..7

    // corner in low 2 lane bits -> lanes 0/1 (x0,x1 of row y0) coalesce into
    // one sector; lanes 2/3 likewise for row y1.
    const int corner = L & 3;
    const int chsub  = wrp * 8 + (L >> 2);   // channel sub-index 0..63

    __shared__ const float* s_base[NENT];
    __shared__ int   s_HW[NENT];
    __shared__ int   s_idx[NENT][4];
    __shared__ float s_w[NENT][4];
    __shared__ int   s_act[NENT];
    __shared__ float s_valid[NCAM];
    __shared__ int   s_list[NENT];
    __shared__ int   s_ne;

    // ---- Phase 1: threads 0..23 build per-(camera,level) sampling entries ----
    if (threadIdx.x < NENT) {
        const int t   = threadIdx.x;
        const int n   = t >> 2;
        const int lvl = t & 3;

        const float* rp = refpts + (size_t)bm * 3;
        float rx = rp[0] * 122.4f - 61.2f;
        float ry = rp[1] * 122.4f - 61.2f;
        float rz = rp[2] * 20.0f  - 10.0f;

        const float* Mt = l2i + (size_t)(b * NCAM + n) * 16;
        float cx = Mt[0]*rx + Mt[1]*ry + Mt[2] *rz + Mt[3];
        float cy = Mt[4]*rx + Mt[5]*ry + Mt[6] *rz + Mt[7];
        float cz = Mt[8]*rx + Mt[9]*ry + Mt[10]*rz + Mt[11];

        bool vcam = (cz > EPSV);
        if (lvl == 0) s_valid[n] = vcam ? 1.0f : 0.0f;

        float inv = 1.0f / (cz + EPSV);
        float x = cx * inv - 0.5f;   // grid_sample denorm cancels across levels
        float y = cy * inv - 0.5f;

        const int W  = c_W[lvl];
        const int H  = c_H[lvl];
        const int HW = c_HW[lvl];

        int active = 0;
        if (vcam && (x > -1.0f) && (x < (float)W) && (y > -1.0f) && (y < (float)H)) {
            float x0f = floorf(x), y0f = floorf(y);
            float wx1 = x - x0f, wx0 = 1.0f - wx1;
            float wy1 = y - y0f, wy0 = 1.0f - wy1;

            bool vx0 = (x0f >= 0.0f)        && (x0f <= (float)(W - 1));
            bool vx1 = (x0f + 1.0f >= 0.0f) && (x0f + 1.0f <= (float)(W - 1));
            bool vy0 = (y0f >= 0.0f)        && (y0f <= (float)(H - 1));
            bool vy1 = (y0f + 1.0f >= 0.0f) && (y0f + 1.0f <= (float)(H - 1));

            int xi0 = (int)fminf(fmaxf(x0f,        0.0f), (float)(W - 1));
            int xi1 = (int)fminf(fmaxf(x0f + 1.0f, 0.0f), (float)(W - 1));
            int yi0 = (int)fminf(fmaxf(y0f,        0.0f), (float)(H - 1));
            int yi1 = (int)fminf(fmaxf(y0f + 1.0f, 0.0f), (float)(H - 1));

            float w00 = (vx0 && vy0) ? (wx0 * wy0) : 0.0f;
            float w01 = (vx1 && vy0) ? (wx1 * wy0) : 0.0f;
            float w10 = (vx0 && vy1) ? (wx0 * wy1) : 0.0f;
            float w11 = (vx1 && vy1) ? (wx1 * wy1) : 0.0f;

            if ((w00 != 0.0f) || (w01 != 0.0f) || (w10 != 0.0f) || (w11 != 0.0f)) {
                active = 1;
                const float* fl = (lvl == 0) ? f0 : (lvl == 1) ? f1 : (lvl == 2) ? f2 : f3;
                s_base[t]   = fl + (size_t)(b * NCAM + n) * CCH * HW;
                s_HW[t]     = HW;
                s_idx[t][0] = yi0 * W + xi0;
                s_idx[t][1] = yi0 * W + xi1;
                s_idx[t][2] = yi1 * W + xi0;
                s_idx[t][3] = yi1 * W + xi1;
                s_w[t][0] = w00;  s_w[t][1] = w01;
                s_w[t][2] = w10;  s_w[t][3] = w11;
            }
        }
        s_act[t] = active;
    }
    __syncthreads();

    if (threadIdx.x == 0) {
        int ne = 0;
        #pragma unroll
        for (int e = 0; e < NENT; e++)
            if (s_act[e]) s_list[ne++] = e;
        s_ne = ne;
    }
    __syncthreads();

    const float cnt = s_valid[0] + s_valid[1] + s_valid[2] +
                      s_valid[3] + s_valid[4] + s_valid[5];
    const int ne = s_ne;

    // ---- Phase 2: per-lane weighted accumulation; butterfly deferred to the
    //      end (quad-sum is linear). Unrolled x2 -> 8 independent LDGs/iter. ----
    float acc0 = 0.0f, acc1 = 0.0f, acc2 = 0.0f, acc3 = 0.0f;

    int k = 0;
    for (; k + 1 < ne; k += 2) {
        const int ea = s_list[k];
        const int eb = s_list[k + 1];
        const int HWa = s_HW[ea];
        const int HWb = s_HW[eb];
        const float wa = s_w[ea][corner];
        const float wb = s_w[eb][corner];
        const float* pa = s_base[ea] + (size_t)chsub * HWa + s_idx[ea][corner];
        const float* pb = s_base[eb] + (size_t)chsub * HWb + s_idx[eb][corner];

        float a0 = __ldg(pa);
        float a1 = __ldg(pa + (size_t)64  * HWa);
        float a2 = __ldg(pa + (size_t)128 * HWa);
        float a3 = __ldg(pa + (size_t)192 * HWa);
        float b0 = __ldg(pb);
        float b1 = __ldg(pb + (size_t)64  * HWb);
        float b2 = __ldg(pb + (size_t)128 * HWb);
        float b3 = __ldg(pb + (size_t)192 * HWb);

        acc0 += a0 * wa;  acc1 += a1 * wa;
        acc2 += a2 * wa;  acc3 += a3 * wa;
        acc0 += b0 * wb;  acc1 += b1 * wb;
        acc2 += b2 * wb;  acc3 += b3 * wb;
    }
    if (k < ne) {
        const int ea = s_list[k];
        const int HWa = s_HW[ea];
        const float wa = s_w[ea][corner];
        const float* pa = s_base[ea] + (size_t)chsub * HWa + s_idx[ea][corner];
        acc0 += __ldg(pa)                    * wa;
        acc1 += __ldg(pa + (size_t)64  * HWa) * wa;
        acc2 += __ldg(pa + (size_t)128 * HWa) * wa;
        acc3 += __ldg(pa + (size_t)192 * HWa) * wa;
    }

    // single butterfly at the end: sum the 4 corners within each quad
    acc0 += __shfl_xor_sync(0xFFFFFFFFu, acc0, 1);
    acc1 += __shfl_xor_sync(0xFFFFFFFFu, acc1, 1);
    acc2 += __shfl_xor_sync(0xFFFFFFFFu, acc2, 1);
    acc3 += __shfl_xor_sync(0xFFFFFFFFu, acc3, 1);
    acc0 += __shfl_xor_sync(0xFFFFFFFFu, acc0, 2);
    acc1 += __shfl_xor_sync(0xFFFFFFFFu, acc1, 2);
    acc2 += __shfl_xor_sync(0xFFFFFFFFu, acc2, 2);
    acc3 += __shfl_xor_sync(0xFFFFFFFFu, acc3, 2);

    if (corner == 0) {
        const float s = 0.25f / (cnt + EPSV);
        float* o = out + (size_t)bm * CCH + chsub;
        o[0]   = acc0 * s;
        o[64]  = acc1 * s;
        o[128] = acc2 * s;
        o[192] = acc3 * s;
    }
}

extern "C" void kernel_launch(void* const* d_in, const int* in_sizes, int n_in,
                              void* d_out, int out_size)
{
    const float* f0  = (const float*)d_in[0];
    const float* f1  = (const float*)d_in[1];
    const float* f2  = (const float*)d_in[2];
    const float* f3  = (const float*)d_in[3];
    const float* rp  = (const float*)d_in[4];
    const float* l2i = (const float*)d_in[5];
    float* out = (float*)d_out;

    dim3 grid(BQ * MQ);
    dim3 block(CCH);
    FeatureSampler_kernel<<<grid, block>>>(f0, f1, f2, f3, rp, l2i, out);
}